// round 8
// baseline (speedup 1.0000x reference)
#include <cuda_runtime.h>
#include <cuda_bf16.h>
#include <cstdint>

// Problem constants
#define Bb    32
#define Ll    4096
#define Cc    128
#define OUTD  257          // 1 delta + 128 probs + 128 amt
#define CL    32           // stored rows per block (one independent tile)
#define HALO  160          // 0.9^160 ~ 5e-8 -> far below 1e-3 tolerance
#define MAXN  (CL + HALO)  // 192
#define TT    16           // q-space subtile (rescale period)

#define MOM   0.9f
#define OMM   0.1f
#define LOG2_MOM (-0.15200309344504995f)   // log2(0.9)

__device__ __forceinline__ uint32_t smem_u32(const void* p) {
    uint32_t a;
    asm("{ .reg .u64 t; cvta.to.shared.u64 t, %1; cvt.u32.u64 %0, t; }"
        : "=r"(a) : "l"(p));
    return a;
}

__global__ __launch_bounds__(160, 6)
void mpe_kernel(const float* __restrict__ ts,
                const int*   __restrict__ labels,
                const float* __restrict__ amounts,
                float*       __restrict__ out)
{
    __shared__ int   s_lab[MAXN];
    __shared__ float s_amt[MAXN];
    __shared__ float s_dl[MAXN];
    __shared__ float s_pacc[Cc];
    __shared__ float s_aacc[Cc];
    __shared__ float s_dacc;
    __shared__ __align__(16) float s_out[CL * OUTD];   // 32 rows staged

    // 0.9^(j+1) and 0.1*0.9^-(j+1): immediates in the unrolled subtile
    constexpr float SC[16] = {
        0.9f, 0.81f, 0.729f, 0.6561f, 0.59049f, 0.531441f, 0.4782969f,
        0.43046721f, 0.387420489f, 0.3486784401f, 0.31381059609f,
        0.282429536481f, 0.2541865828329f, 0.22876792454961f,
        0.205891132094649f, 0.1853020188851841f };
    constexpr float WC[16] = {
        0.111111111111111f, 0.123456790123457f, 0.137174211248285f,
        0.152415790275873f, 0.169350878084303f, 0.188167642315892f,
        0.209075158128769f, 0.232305731254188f, 0.258117479171320f,
        0.286797199079244f, 0.318663554532493f, 0.354070616147215f,
        0.393411795719128f, 0.437124217465697f, 0.485693574961886f,
        0.539659527735429f };

    const int chunk = blockIdx.x;
    const int b     = blockIdx.y;
    const int t0    = chunk * CL;
    const int s0    = (t0 - HALO) > 0 ? (t0 - HALO) : 0;
    const int N     = t0 + CL - s0;
    const int warm  = t0 - s0;
    const int tid   = threadIdx.x;

    const float* tsb = ts      + (size_t)b * Ll;
    const int*   lb  = labels  + (size_t)b * Ll;
    const float* ab  = amounts + (size_t)b * Ll;

    // ---- zero accumulators + cooperative preload (<=2 items/thread) ----
    if (tid < Cc)       { s_pacc[tid] = 0.0f; s_aacc[tid] = 0.0f; }
    else if (tid == Cc) { s_dacc = 0.0f; }

    for (int i = tid; i < N; i += blockDim.x) {
        const int g = s0 + i;
        s_lab[i] = lb[g];
        s_amt[i] = ab[g];
        float d = 0.0f;
        if (g > 0) d = fminf(tsb[g] - tsb[g - 1], 100.0f);
        s_dl[i] = d;
    }
    __syncthreads();

    // ---- warm-up via weighted scatter: state = sum_i 0.1*0.9^(warm-1-i)*x_i ----
    if (warm > 0) {
        float dsum = 0.0f;
        for (int i = tid; i < warm; i += blockDim.x) {
            const float w = OMM * exp2f((float)(warm - 1 - i) * LOG2_MOM);
            atomicAdd(&s_pacc[s_lab[i]], w);
            atomicAdd(&s_aacc[s_lab[i]], w * s_amt[i]);
            dsum = fmaf(w, s_dl[i], dsum);
        }
        // warp-reduce delta partials, one atomic per warp
        #pragma unroll
        for (int off = 16; off > 0; off >>= 1)
            dsum += __shfl_xor_sync(0xffffffffu, dsum, off);
        if ((tid & 31) == 0) atomicAdd(&s_dacc, dsum);

        if (s0 == 0 && tid == 0) {
            // exact-start init: carry = x0 contributes 0.9^warm * x0
            const float w0 = exp2f((float)warm * LOG2_MOM);
            atomicAdd(&s_pacc[s_lab[0]], w0);
            atomicAdd(&s_aacc[s_lab[0]], w0 * s_amt[0]);
            // delta: dl[0] == 0 -> no init term
        }
        __syncthreads();
    }

    // ---- per-thread scan state (q-space) ----
    float q = 0.0f, qa = 0.0f, r = 0.0f, dcar = 0.0f;
    const int c = tid;
    if (tid < Cc) {
        float p0, a0;
        if (warm == 0) {            // chunk 0: exact carry-init (y[0] = x[0])
            const bool eq0 = (s_lab[0] == c);
            p0 = eq0 ? 1.0f : 0.0f;
            a0 = eq0 ? s_amt[0] : 0.0f;
        } else {
            p0 = s_pacc[tid];
            a0 = s_aacc[tid];
        }
        q  = p0;
        qa = a0;
        r  = __fdividef(a0, fmaxf(p0, 1e-30f));  // a0==0 when p0==0 -> r=0
    } else if (tid == Cc) {
        dcar = s_dacc;              // ==0 for chunk 0
    }

    // ---- 32 stored rows: sparse-hit scan into smem ----
    if (tid < Cc) {
        #pragma unroll
        for (int sub = 0; sub < CL / TT; sub++) {
            const int base = warm + sub * TT;
            float* ob = s_out + sub * TT * OUTD;
            #pragma unroll
            for (int j = 0; j < TT; j++) {
                const bool eq = (s_lab[base + j] == c);
                if (__ballot_sync(0xffffffffu, eq)) {   // warp-uniform skip
                    if (eq) {
                        q  += WC[j];
                        qa  = fmaf(s_amt[base + j], WC[j], qa);
                        r = __fdividef(SC[j] * qa, SC[j] * q);  // p at hit >= 0.1
                    }
                }
                const float pj  = SC[j] * q;            // probs (sum==1)
                const float a6  = (SC[j] * 1e6f) * qa;  // a / 1e-6
                const float amt = fminf(r, a6);         // == a/max(p,1e-6)
                ob[j * OUTD + 1 + c]      = pj;
                ob[j * OUTD + 1 + Cc + c] = amt;
            }
            q  *= SC[TT - 1];   // rescale to true state space
            qa *= SC[TT - 1];
        }
    } else if (tid == Cc) {
        #pragma unroll
        for (int j = 0; j < CL; j++) {
            dcar = MOM * dcar + OMM * s_dl[warm + j];
            s_out[j * OUTD] = dcar;
        }
    }
    __syncthreads();   // tile fully staged

    // ---- one bulk copy of the whole tile (32 * 1028 B = 32,896 B) ----
    if (tid == Cc + 1) {
        asm volatile("fence.proxy.async.shared::cta;" ::: "memory");
        const uint64_t gdst = (uint64_t)(out + (size_t)(b * Ll + t0) * OUTD);
        const uint32_t ssrc = smem_u32(s_out);
        asm volatile("cp.async.bulk.global.shared::cta.bulk_group [%0], [%1], %2;"
                     :: "l"(gdst), "r"(ssrc), "r"((uint32_t)(CL * OUTD * 4))
                     : "memory");
        asm volatile("cp.async.bulk.commit_group;" ::: "memory");
        asm volatile("cp.async.bulk.wait_group 0;" ::: "memory");
    }
    __syncthreads();   // no thread exits while the copy reads smem
}

extern "C" void kernel_launch(void* const* d_in, const int* in_sizes, int n_in,
                              void* d_out, int out_size)
{
    const float* ts      = (const float*)d_in[0];
    const int*   labels  = (const int*)  d_in[1];
    const float* amounts = (const float*)d_in[2];
    float* out = (float*)d_out;

    dim3 grid(Ll / CL, Bb);   // (128, 32) = 4096 blocks
    dim3 block(160);
    mpe_kernel<<<grid, block>>>(ts, labels, amounts, out);
}

// round 10
// speedup vs baseline: 1.0606x; 1.0606x over previous
#include <cuda_runtime.h>
#include <cuda_bf16.h>
#include <cstdint>

// Problem constants
#define Bb    32
#define Ll    4096
#define Cc    128
#define OUTD  257          // 1 delta + 128 probs + 128 amt
#define CL    256          // stored steps per block
#define HALO  192          // 0.9^192 ~ 1.6e-9 -> below fp32 noise
#define MAXN  (CL + HALO)  // 448
#define TT    8            // rows per staged tile / q-space rescale period
#define NTILE (CL / TT)    // 32
#define WTILE (HALO / TT)  // 24

#define MOM   0.9f
#define OMM   0.1f

__device__ __forceinline__ uint32_t smem_u32(const void* p) {
    uint32_t a;
    asm("{ .reg .u64 t; cvta.to.shared.u64 t, %1; cvt.u32.u64 %0, t; }"
        : "=r"(a) : "l"(p));
    return a;
}

__global__ __launch_bounds__(160, 6)
void mpe_kernel(const float* __restrict__ ts,
                const int*   __restrict__ labels,
                const float* __restrict__ amounts,
                float*       __restrict__ out)
{
    __shared__ int   s_lab[MAXN];                       // labels
    __shared__ float s_amt[MAXN];                       // amounts
    __shared__ float s_dl[MAXN];                        // clipped deltas
    __shared__ __align__(16) float s_out[2][TT * OUTD]; // staged output rows

    // SC[j] = 0.9^(j+1), WC[j] = 0.1 * 0.9^-(j+1): immediates after unroll
    constexpr float SC[8] = {
        0.9f, 0.81f, 0.729f, 0.6561f, 0.59049f, 0.531441f,
        0.4782969f, 0.43046721f };
    constexpr float WC[8] = {
        0.111111111111111f, 0.123456790123457f, 0.137174211248285f,
        0.152415790275873f, 0.169350878084303f, 0.188167642315892f,
        0.209075158128769f, 0.232305731254188f };

    const int chunk = blockIdx.x;
    const int b     = blockIdx.y;
    const int t0    = chunk * CL;
    const int s0    = (t0 - HALO) > 0 ? (t0 - HALO) : 0;
    const int N     = t0 + CL - s0;
    const int warm  = t0 - s0;                          // 0 (chunk 0) or 192
    const int tid   = threadIdx.x;

    const float* tsb = ts      + (size_t)b * Ll;
    const int*   lb  = labels  + (size_t)b * Ll;
    const float* ab  = amounts + (size_t)b * Ll;

    // ---- cooperative preload of the window into smem ----
    for (int i = tid; i < N; i += blockDim.x) {
        const int g = s0 + i;
        s_lab[i] = lb[g];
        s_amt[i] = ab[g];
        float d = 0.0f;
        if (g > 0) d = fminf(tsb[g] - tsb[g - 1], 100.0f);
        s_dl[i] = d;
    }
    __syncthreads();

    // ---- per-thread state (q-space) ----
    float q = 0.0f, qa = 0.0f, r = 0.0f, dcar = 0.0f;
    const int c = tid;

    if (tid < Cc) {
        if (warm == 0) {
            // chunk 0: exact carry-init (row 0 then emits exactly x0)
            const bool eq0 = (s_lab[0] == c);
            q  = eq0 ? 1.0f : 0.0f;
            qa = eq0 ? s_amt[0] : 0.0f;
            r  = eq0 ? __fdividef(qa, q) : 0.0f;
        } else {
            // ---- sparse-hit warm-up: no stores, no divides, no FFMA chain ----
            #pragma unroll 1
            for (int wt = 0; wt < WTILE; wt++) {
                const int base = wt * TT;
                #pragma unroll
                for (int j = 0; j < TT; j++) {
                    const bool eq = (s_lab[base + j] == c);
                    if (__ballot_sync(0xffffffffu, eq)) {   // warp-uniform skip
                        if (eq) {
                            q  += WC[j];
                            qa  = fmaf(s_amt[base + j], WC[j], qa);
                        }
                    }
                }
                q  *= SC[TT - 1];   // rescale to true state space
                qa *= SC[TT - 1];
            }
            r = __fdividef(qa, fmaxf(q, 1e-30f));  // qa==0 when q==0 -> r=0
        }
    } else if (tid == Cc) {
        // dense delta warm-up (serial scalar chain; cheap)
        #pragma unroll 8
        for (int i = 0; i < warm; i++)
            dcar = MOM * dcar + OMM * s_dl[i];
    }

    // ---- stored steps: sparse-hit scan into smem tiles, bulk-copy drain ----
    const char* gbase = (const char*)(out + (size_t)(b * Ll + t0) * OUTD);
    int pb = 0;
    for (int tile = 0; tile < NTILE; tile++) {
        float* ob = s_out[pb];
        const int base = warm + tile * TT;

        if (tid < Cc) {
            #pragma unroll
            for (int j = 0; j < TT; j++) {
                const bool eq = (s_lab[base + j] == c);
                if (__ballot_sync(0xffffffffu, eq)) {   // ~78% of steps skip
                    if (eq) {
                        q  += WC[j];                          // 0.1*0.9^-(j+1)
                        qa  = fmaf(s_amt[base + j], WC[j], qa);
                        r = __fdividef(SC[j] * qa, SC[j] * q); // p at hit >= 0.1
                    }
                }
                const float pj  = SC[j] * q;            // probs (sum==1)
                const float a6  = (SC[j] * 1e6f) * qa;  // a / 1e-6
                const float amt = fminf(r, a6);         // == a/max(p,1e-6)
                ob[j * OUTD + 1 + c]      = pj;
                ob[j * OUTD + 1 + Cc + c] = amt;
            }
            q  *= SC[TT - 1];   // rescale back to true state space
            qa *= SC[TT - 1];
        } else if (tid == Cc) {
            const float* dl = s_dl + base;
            #pragma unroll
            for (int j = 0; j < TT; j++) {
                dcar = MOM * dcar + OMM * dl[j];
                ob[j * OUTD] = dcar;
            }
        }
        __syncthreads();   // tile fully written

        if (tid == Cc + 1) {
            asm volatile("fence.proxy.async.shared::cta;" ::: "memory");
            const uint64_t gdst = (uint64_t)(gbase + (size_t)tile * TT * OUTD * 4);
            const uint32_t ssrc = smem_u32(ob);
            asm volatile("cp.async.bulk.global.shared::cta.bulk_group [%0], [%1], %2;"
                         :: "l"(gdst), "r"(ssrc), "r"((uint32_t)(TT * OUTD * 4))
                         : "memory");
            asm volatile("cp.async.bulk.commit_group;" ::: "memory");
            asm volatile("cp.async.bulk.wait_group 1;" ::: "memory");
        }
        __syncthreads();   // other buffer drained -> reusable
        pb ^= 1;
    }

    if (tid == Cc + 1)
        asm volatile("cp.async.bulk.wait_group 0;" ::: "memory");
}

extern "C" void kernel_launch(void* const* d_in, const int* in_sizes, int n_in,
                              void* d_out, int out_size)
{
    const float* ts      = (const float*)d_in[0];
    const int*   labels  = (const int*)  d_in[1];
    const float* amounts = (const float*)d_in[2];
    float* out = (float*)d_out;

    dim3 grid(Ll / CL, Bb);   // (16, 32) = 512 blocks
    dim3 block(160);
    mpe_kernel<<<grid, block>>>(ts, labels, amounts, out);
}

// round 11
// speedup vs baseline: 1.1406x; 1.0755x over previous
#include <cuda_runtime.h>
#include <cuda_bf16.h>
#include <cstdint>

// Problem constants
#define Bb    32
#define Ll    4096
#define Cc    128
#define OUTD  257          // 1 delta + 128 probs + 128 amt
#define CL    256          // stored steps per block
#define HALO  192          // 0.9^192 ~ 1.6e-9 -> below fp32 noise
#define MAXN  (CL + HALO)  // 448
#define TT    8            // rows per staged tile
#define NTILE (CL / TT)    // 32
#define NBUF  6            // staging ring depth (5 copies in flight)

#define MOM   0.9f
#define OMM   0.1f

__device__ __forceinline__ uint32_t smem_u32(const void* p) {
    uint32_t a;
    asm("{ .reg .u64 t; cvta.to.shared.u64 t, %1; cvt.u32.u64 %0, t; }"
        : "=r"(a) : "l"(p));
    return a;
}

__global__ __launch_bounds__(160, 4)
void mpe_kernel(const float* __restrict__ ts,
                const int*   __restrict__ labels,
                const float* __restrict__ amounts,
                float*       __restrict__ out)
{
    __shared__ uint2 s_la[MAXN];                           // .x=label, .y=bits(0.1*amount)
    __shared__ float s_dl[MAXN];                           // clipped deltas
    __shared__ __align__(16) float s_out[NBUF][TT * OUTD]; // staging ring

    const int chunk = blockIdx.x;
    const int b     = blockIdx.y;
    const int t0    = chunk * CL;
    const int s0    = (t0 - HALO) > 0 ? (t0 - HALO) : 0;
    const int N     = t0 + CL - s0;
    const int warm  = t0 - s0;                             // 0 (chunk 0) or 192
    const int tid   = threadIdx.x;

    const float* tsb = ts      + (size_t)b * Ll;
    const int*   lb  = labels  + (size_t)b * Ll;
    const float* ab  = amounts + (size_t)b * Ll;

    // ---- cooperative preload (amounts pre-scaled by 0.1) ----
    for (int i = tid; i < N; i += blockDim.x) {
        const int g = s0 + i;
        s_la[i] = make_uint2((unsigned)lb[g], __float_as_uint(OMM * ab[g]));
        float d = 0.0f;
        if (g > 0) d = fminf(tsb[g] - tsb[g - 1], 100.0f);
        s_dl[i] = d;
    }
    __syncthreads();

    // ---- per-thread state ----
    float p = 0.0f, a = 0.0f, dcar = 0.0f;
    const int c = tid;

    if (tid < Cc) {
        if (warm == 0) {
            // chunk 0 carry-init: row 0 then emits exactly x0
            // (p: 0.9*1 + 0.1 = 1; a: 0.9*a0 + 0.1*a0 = a0)
            const uint2 la0 = s_la[0];
            const bool eq0 = ((int)la0.x == c);
            p = eq0 ? 1.0f : 0.0f;
            a = eq0 ? 10.0f * __uint_as_float(la0.y) : 0.0f;
        } else {
            // dense branchless warm-up
            #pragma unroll 8
            for (int i = 0; i < warm; i++) {
                const uint2 v = s_la[i];
                const bool eq = ((int)v.x == c);
                p = MOM * p + (eq ? OMM : 0.0f);
                a = MOM * a + (eq ? __uint_as_float(v.y) : 0.0f);
            }
        }
    } else if (tid == Cc) {
        #pragma unroll 8
        for (int i = 0; i < warm; i++)
            dcar = MOM * dcar + OMM * s_dl[i];
    }

    // ---- stored steps: dense scan into 6-deep staging ring, async drain ----
    const char* gbase = (const char*)(out + (size_t)(b * Ll + t0) * OUTD);
    for (int tile = 0; tile < NTILE; tile++) {
        float* ob = s_out[tile % NBUF];
        const int base = warm + tile * TT;

        if (tid < Cc) {
            const uint2* la = s_la + base;
            #pragma unroll
            for (int j = 0; j < TT; j++) {
                const uint2 v = la[j];
                const bool eq = ((int)v.x == c);
                p = MOM * p + (eq ? OMM : 0.0f);
                a = MOM * a + (eq ? __uint_as_float(v.y) : 0.0f);
                ob[j * OUTD + 1 + c]      = p;                              // probs (sum==1)
                ob[j * OUTD + 1 + Cc + c] = __fdividef(a, fmaxf(p, 1e-6f)); // amt
            }
        } else if (tid == Cc) {
            const float* dl = s_dl + base;
            #pragma unroll
            for (int j = 0; j < TT; j++) {
                dcar = MOM * dcar + OMM * dl[j];
                ob[j * OUTD] = dcar;
            }
        }
        __syncthreads();   // tile fully written

        if (tid == Cc + 1) {
            asm volatile("fence.proxy.async.shared::cta;" ::: "memory");
            const uint64_t gdst = (uint64_t)(gbase + (size_t)tile * TT * OUTD * 4);
            const uint32_t ssrc = smem_u32(ob);
            asm volatile("cp.async.bulk.global.shared::cta.bulk_group [%0], [%1], %2;"
                         :: "l"(gdst), "r"(ssrc), "r"((uint32_t)(TT * OUTD * 4))
                         : "memory");
            asm volatile("cp.async.bulk.commit_group;" ::: "memory");
            // allow 5 copies in flight: guarantees copy (tile-5) done, so the
            // buffer reused at (tile+1) [== tile-5 mod 6] is free. Completion
            // latency is amortized over 5 tiles instead of exposed every tile.
            asm volatile("cp.async.bulk.wait_group 5;" ::: "memory");
        }
        __syncthreads();   // reuse-safety broadcast
    }

    if (tid == Cc + 1)
        asm volatile("cp.async.bulk.wait_group 0;" ::: "memory");
    __syncthreads();       // keep smem alive until all copies land
}

extern "C" void kernel_launch(void* const* d_in, const int* in_sizes, int n_in,
                              void* d_out, int out_size)
{
    const float* ts      = (const float*)d_in[0];
    const int*   labels  = (const int*)  d_in[1];
    const float* amounts = (const float*)d_in[2];
    float* out = (float*)d_out;

    dim3 grid(Ll / CL, Bb);   // (16, 32) = 512 blocks
    dim3 block(160);
    mpe_kernel<<<grid, block>>>(ts, labels, amounts, out);
}